// round 12
// baseline (speedup 1.0000x reference)
#include <cuda_runtime.h>
#include <math.h>
#include <stdint.h>

#define HH    64
#define DIMC  512     // per-axis sinusoid width
#define ODIM  256     // output dim
#define BATCH 8
#define NSPLIT 16     // split-K chunks (32 k each)
#define K2_BLOCKS 256 // k2 grid = (64, 4)
#define NCNT 32       // distributed ticket words

// C[r][o]: r<64 -> A[h][o] (W cols 0:512), r>=64 -> B[w][o] (W cols 512:1024).
// Static-zero at load; k2's idempotent epilogue re-zeroes it after every use.
__device__ float        g_C[2 * HH][ODIM];
__device__ unsigned int g_cnt[NCNT];   // distributed exit tickets (reset by zeroer)

// ---------------------------------------------------------------------------
// k1: fused embed + split-K GEMM, REDG accumulation into g_C (measured 5.6us
// as first kernel incl. clock ramp). grid (16 kc, 4 nt, 2 half) x 256 thr.
// ---------------------------------------------------------------------------
__global__ __launch_bounds__(256) void k1_embed_gemm(const float* __restrict__ W) {
    const int k0   = blockIdx.x * 32;
    const int n0   = blockIdx.y * 64;
    const int half = blockIdx.z;
    const int off  = half * DIMC;

    __shared__ float fr[32];
    __shared__ float Et[32][68];    // [k][m] transposed embed tile, padded
    __shared__ float Ws[32][68];    // [k][n] padded

    const int t = threadIdx.x;

    if (t < 32) {
        int c = k0 + t;
        float expo = (c < 256) ? (float)(2 * c + 1) * (1.0f / 512.0f)
                               : (float)(2 * (c - 256)) * (1.0f / 512.0f);
        fr[t] = __expf(-expo * 6.907755278982137f);   // 1000^(-expo)
    }
    __syncthreads();

    // embed tile transposed: Et[kk][m], coalesced over m
    #pragma unroll
    for (int e = t; e < 32 * 64; e += 256) {
        int m = e & 63, kk = e >> 6;
        float zf = (float)m * fr[kk];
        Et[kk][m] = (k0 + kk < 256) ? __sinf(zf) : __cosf(zf);
    }
    // stage W tile (transposed): rows n0..n0+63, cols k0..k0+31, coalesced over k
    #pragma unroll
    for (int e = t; e < 64 * 32; e += 256) {
        int kk = e & 31, i = e >> 5;
        Ws[kk][i] = W[(size_t)(n0 + i) * (2 * DIMC) + off + k0 + kk];
    }
    __syncthreads();

    const int tx = t & 15, ty = t >> 4;    // 16 x 16 threads
    const int mb = ty * 4, nb = tx * 4;    // 4x4 micro-tile

    float acc[4][4] = {};
    #pragma unroll 8
    for (int k = 0; k < 32; k++) {
        float4 a = *(const float4*)&Et[k][mb];
        float4 b = *(const float4*)&Ws[k][nb];
        acc[0][0] += a.x * b.x; acc[0][1] += a.x * b.y; acc[0][2] += a.x * b.z; acc[0][3] += a.x * b.w;
        acc[1][0] += a.y * b.x; acc[1][1] += a.y * b.y; acc[1][2] += a.y * b.z; acc[1][3] += a.y * b.w;
        acc[2][0] += a.z * b.x; acc[2][1] += a.z * b.y; acc[2][2] += a.z * b.z; acc[2][3] += a.z * b.w;
        acc[3][0] += a.w * b.x; acc[3][1] += a.w * b.y; acc[3][2] += a.w * b.z; acc[3][3] += a.w * b.w;
    }

    const int rbase = half * 64 + mb;
    #pragma unroll
    for (int i = 0; i < 4; i++)
        #pragma unroll
        for (int j = 0; j < 4; j++)
            atomicAdd(&g_C[rbase + i][n0 + nb + j], acc[i][j]);   // REDG, distinct addrs
}

// ---------------------------------------------------------------------------
// k2: broadcast write (38 MB total L2 traffic) + idempotent distributed-ticket
// epilogue that re-zeroes g_C for the next replay.
//   out[b][h][w][o] = C[h][o] + C[64+w][o]
// block (h, wq): w in [wq*16, wq*16+16), all 8 batches. grid (64,4) x 256 thr.
// ---------------------------------------------------------------------------
__global__ __launch_bounds__(256) void k2_write(float* __restrict__ out) {
    const int t  = threadIdx.x;
    const int q  = t & 63;        // float4 column (o = 4q)
    const int rg = t >> 6;        // 0..3 -> 4 w-rows each
    const int h  = blockIdx.x;    // 0..63
    const int wq = blockIdx.y;    // 0..3
    const int bid = blockIdx.y * 64 + blockIdx.x;   // 0..255

    const size_t colo = (size_t)q * 4;
    float4 a = *(const float4*)&g_C[h][colo];

    #pragma unroll
    for (int i = 0; i < 4; i++) {
        int w = wq * 16 + rg * 4 + i;
        float4 e = *(const float4*)&g_C[64 + w][colo];
        float4 v;
        v.x = a.x + e.x; v.y = a.y + e.y; v.z = a.z + e.z; v.w = a.w + e.w;

        size_t base = (((size_t)h * HH + w) * ODIM) + colo;
        const size_t bstride = (size_t)HH * HH * ODIM;
        #pragma unroll
        for (int b = 0; b < BATCH; b++)
            *(float4*)&out[base + (size_t)b * bstride] = v;
    }

    // ---- idempotent distributed-ticket epilogue -----------------------------
    // By here every thread's g_C loads completed (consumed by the stores above).
    __syncthreads();
    __shared__ unsigned int ssum;
    if (t == 0) {
        atomicAdd(&g_cnt[bid & (NCNT - 1)], 1u);   // 8 RMWs per word: cheap
        __threadfence();
        unsigned s = 0;
        #pragma unroll
        for (int i = 0; i < NCNT; i++)
            s += __ldcg(&g_cnt[i]);                // plain L2 reads: no RMW serialization
        ssum = s;
    }
    __syncthreads();

    if (ssum == (unsigned)K2_BLOCKS) {
        // All 256 blocks have incremented => all g_C reads done. Zeroing is
        // idempotent, so multiple concurrent zeroers are harmless; the
        // real-time-last incrementer is guaranteed to see 256 (>=1 zeroer).
        float4 z4 = make_float4(0.f, 0.f, 0.f, 0.f);
        float4* cp = (float4*)g_C;
        #pragma unroll
        for (int i = t; i < (2 * HH * ODIM) / 4; i += 256)
            cp[i] = z4;
        __syncthreads();
        if (t == 0) {
            __threadfence();
            #pragma unroll
            for (int i = 0; i < NCNT; i++)
                g_cnt[i] = 0;          // visible to next launch via kernel boundary
        }
    }
}

// ---------------------------------------------------------------------------
extern "C" void kernel_launch(void* const* d_in, const int* in_sizes, int n_in,
                              void* d_out, int out_size) {
    const float* W = (const float*)d_in[0];   // W_im: (256, 1024) fp32
    float* out = (float*)d_out;               // (8, 64, 64, 256, 1) fp32

    dim3 g1(NSPLIT, 4, 2);
    k1_embed_gemm<<<g1, 256>>>(W);
    dim3 g2(HH, 4);
    k2_write<<<g2, 256>>>(out);
}

// round 13
// speedup vs baseline: 1.4537x; 1.4537x over previous
#include <cuda_runtime.h>
#include <math.h>
#include <stdint.h>

#define HH    64
#define DIMC  512     // per-axis sinusoid width
#define ODIM  256     // output dim
#define BATCH 8
#define NSPLIT 16     // split-K chunks (32 k each)

// C[r][o]: r<64 -> A[h][o] (W cols 0:512), r>=64 -> B[w][o] (W cols 512:1024).
// Invariant: g_C == 0 at every kernel_launch entry. Static init covers the
// first call; k3 (launched after k2) restores it for the next call/replay.
__device__ float g_C[2 * HH][ODIM];

// ---------------------------------------------------------------------------
// k1: fused embed + split-K GEMM, REDG atomicAdd into g_C (distinct addresses).
//   C[half*64+m][o] += sum_{k in chunk} embed(m)[k] * W[o][half*512+k]
// grid (16 kc, 4 ntiles, 2 halves) = 128 blocks x 256 threads.
// Measured 5.6us as first kernel (absorbs graph-start clock ramp).
// ---------------------------------------------------------------------------
__global__ __launch_bounds__(256) void k1_embed_gemm(const float* __restrict__ W) {
    const int k0   = blockIdx.x * 32;
    const int n0   = blockIdx.y * 64;
    const int half = blockIdx.z;
    const int off  = half * DIMC;

    __shared__ float fr[32];
    __shared__ float Et[32][68];    // [k][m] transposed embed tile, padded
    __shared__ float Ws[32][68];    // [k][n] padded

    const int t = threadIdx.x;

    if (t < 32) {
        int c = k0 + t;
        float expo = (c < 256) ? (float)(2 * c + 1) * (1.0f / 512.0f)
                               : (float)(2 * (c - 256)) * (1.0f / 512.0f);
        fr[t] = __expf(-expo * 6.907755278982137f);   // 1000^(-expo)
    }
    __syncthreads();

    // embed tile transposed: Et[kk][m]
    #pragma unroll
    for (int e = t; e < 32 * 64; e += 256) {
        int m = e & 63, kk = e >> 6;
        float zf = (float)m * fr[kk];
        Et[kk][m] = (k0 + kk < 256) ? __sinf(zf) : __cosf(zf);
    }
    // stage W tile (transposed): rows n0..n0+63, cols k0..k0+31, coalesced over k
    #pragma unroll
    for (int e = t; e < 64 * 32; e += 256) {
        int kk = e & 31, i = e >> 5;
        Ws[kk][i] = W[(size_t)(n0 + i) * (2 * DIMC) + off + k0 + kk];
    }
    __syncthreads();

    const int tx = t & 15, ty = t >> 4;    // 16 x 16 threads
    const int mb = ty * 4, nb = tx * 4;    // 4x4 micro-tile

    float acc[4][4] = {};
    #pragma unroll 8
    for (int k = 0; k < 32; k++) {
        float4 a = *(const float4*)&Et[k][mb];
        float4 b = *(const float4*)&Ws[k][nb];
        acc[0][0] += a.x * b.x; acc[0][1] += a.x * b.y; acc[0][2] += a.x * b.z; acc[0][3] += a.x * b.w;
        acc[1][0] += a.y * b.x; acc[1][1] += a.y * b.y; acc[1][2] += a.y * b.z; acc[1][3] += a.y * b.w;
        acc[2][0] += a.z * b.x; acc[2][1] += a.z * b.y; acc[2][2] += a.z * b.z; acc[2][3] += a.z * b.w;
        acc[3][0] += a.w * b.x; acc[3][1] += a.w * b.y; acc[3][2] += a.w * b.z; acc[3][3] += a.w * b.w;
    }

    const int rbase = half * 64 + mb;
    #pragma unroll
    for (int i = 0; i < 4; i++)
        #pragma unroll
        for (int j = 0; j < 4; j++)
            atomicAdd(&g_C[rbase + i][n0 + nb + j], acc[i][j]);   // REDG, distinct addrs
}

// ---------------------------------------------------------------------------
// k2: broadcast write, read-amortized, NO epilogue (measured ~7.0us).
//   out[b][h][w][o] = C[h][o] + C[64+w][o]
// block (h, wq): h fixed, w in [wq*16, wq*16+16), ALL 8 batches.
// Reads 17 KB of C per block (4.4 MB total); writes 33.5 MB coalesced STG.128.
// grid (64, 4) = 256 blocks x 256 threads.
// ---------------------------------------------------------------------------
__global__ __launch_bounds__(256) void k2_write(float* __restrict__ out) {
    const int t  = threadIdx.x;
    const int q  = t & 63;        // float4 column (o = 4q)
    const int rg = t >> 6;        // 0..3 -> 4 w-rows each
    const int h  = blockIdx.x;    // 0..63
    const int wq = blockIdx.y;    // 0..3

    const size_t colo = (size_t)q * 4;
    float4 a = *(const float4*)&g_C[h][colo];

    #pragma unroll
    for (int i = 0; i < 4; i++) {
        int w = wq * 16 + rg * 4 + i;
        float4 e = *(const float4*)&g_C[64 + w][colo];
        float4 v;
        v.x = a.x + e.x; v.y = a.y + e.y; v.z = a.z + e.z; v.w = a.w + e.w;

        size_t base = (((size_t)h * HH + w) * ODIM) + colo;
        const size_t bstride = (size_t)HH * HH * ODIM;
        #pragma unroll
        for (int b = 0; b < BATCH; b++)
            *(float4*)&out[base + (size_t)b * bstride] = v;
    }
}

// ---------------------------------------------------------------------------
// k3: trailing zero of g_C (restores the entry invariant for the next launch).
// 32768 floats = 8192 float4; 64 blocks x 128 threads x 1 float4.
// Runs after the ramp is paid -> costs only its tiny launch window.
// ---------------------------------------------------------------------------
__global__ __launch_bounds__(128) void k3_zero() {
    int idx = blockIdx.x * 128 + threadIdx.x;
    ((float4*)g_C)[idx] = make_float4(0.f, 0.f, 0.f, 0.f);
}

// ---------------------------------------------------------------------------
extern "C" void kernel_launch(void* const* d_in, const int* in_sizes, int n_in,
                              void* d_out, int out_size) {
    const float* W = (const float*)d_in[0];   // W_im: (256, 1024) fp32
    float* out = (float*)d_out;               // (8, 64, 64, 256, 1) fp32

    dim3 g1(NSPLIT, 4, 2);
    k1_embed_gemm<<<g1, 256>>>(W);
    dim3 g2(HH, 4);
    k2_write<<<g2, 256>>>(out);
    k3_zero<<<64, 128>>>();
}